// round 1
// baseline (speedup 1.0000x reference)
#include <cuda_runtime.h>
#include <math.h>

#define NTH 512
#define VP 72
#define VROWS 68

// smem layout (in floats)
#define OFF_QR   0          // 8*64*64 = 32768  (aliased by padded maze ints early)
#define OFF_V    32768      // 68*72 = 4896
#define OFF_R    37664      // 68*72 = 4896
#define OFF_WQ   42560      // 200
#define OFF_WW   42760      // 200
#define OFF_FCW  42960      // 32
#define OFF_LT   42992      // 100 (25 taps x 4: maze 0,1,2 + sentinel 3 -> 0)
#define OFF_WE   43092      // 50  (W_eff[2][25])
#define OFF_BE   43142      // 1
#define SMEM_FLOATS 43144
#define SMEM_BYTES (SMEM_FLOATS * 4)

__global__ __launch_bounds__(NTH, 1)
void vin_kernel(const int*   __restrict__ maze,
                const float* __restrict__ emb,
                const float* __restrict__ encode_w,
                const float* __restrict__ encode_b,
                const float* __restrict__ r_w,
                const float* __restrict__ q_w,
                const float* __restrict__ w,
                const float* __restrict__ fc_w,
                float* __restrict__ out)
{
    extern __shared__ float sm[];
    float* qr   = sm + OFF_QR;
    float* vsm  = sm + OFF_V;
    float* rsm  = sm + OFF_R;
    float* wq   = sm + OFF_WQ;
    float* ww   = sm + OFF_WW;
    float* fcw  = sm + OFF_FCW;
    float* Lt   = sm + OFF_LT;
    float* Weff = sm + OFF_WE;
    int*   msm  = (int*)qr;          // 68*68 ints = 4624 < 32768 floats, alias OK

    const int tid = threadIdx.x;
    const int b   = blockIdx.x;
    const int tx  = tid & 15;        // 16 threads across x
    const int ty  = tid >> 4;        // 32 threads across y
    const int x0  = tx * 4;          // each thread: 2 rows x 4 cols
    const int y0  = ty * 2;

    // ---------------- prologue: weights, W_eff, init ----------------
    for (int i = tid; i < 200; i += NTH) { wq[i] = q_w[i]; ww[i] = w[i]; }
    if (tid < 32) fcw[tid] = fc_w[tid];
    if (tid < 50) {
        float s = 0.f;
        #pragma unroll 5
        for (int c = 0; c < 150; ++c) s += r_w[c] * encode_w[c * 50 + tid];
        Weff[tid] = s;
    }
    if (tid == 63) {
        float s = 0.f;
        for (int c = 0; c < 150; ++c) s += r_w[c] * encode_b[c];
        sm[OFF_BE] = s;
    }
    for (int i = tid; i < 68 * 68; i += NTH) msm[i] = 3;       // sentinel border
    for (int i = tid; i < VROWS * VP; i += NTH) { vsm[i] = 0.f; rsm[i] = 0.f; }
    __syncthreads();

    // LUT: Lt[tap*4 + mazeval] = Weff0[tap]*emb[v][0] + Weff1[tap]*emb[v][1]; [3]=0
    if (tid < 75) {
        int t = tid / 3, mv = tid - t * 3;
        Lt[t * 4 + mv] = Weff[t] * emb[mv * 2] + Weff[25 + t] * emb[mv * 2 + 1];
        if (mv == 0) Lt[t * 4 + 3] = 0.f;
    }
    const int* mzg = maze + b * 4096;
    for (int i = tid; i < 4096; i += NTH)
        msm[((i >> 6) + 2) * 68 + (i & 63) + 2] = mzg[i];
    __syncthreads();

    // ---------------- r = LUT-conv(maze) + b_eff ----------------
    {
        int ma[6][8];
        #pragma unroll
        for (int i = 0; i < 6; i++)
            #pragma unroll
            for (int j = 0; j < 8; j++)
                ma[i][j] = msm[(y0 + i) * 68 + x0 + j];
        float bv = sm[OFF_BE];
        float rv[2][4];
        #pragma unroll
        for (int i = 0; i < 2; i++)
            #pragma unroll
            for (int j = 0; j < 4; j++) rv[i][j] = bv;
        #pragma unroll
        for (int ky = 0; ky < 5; ky++)
            #pragma unroll
            for (int kx = 0; kx < 5; kx++) {
                const float* lt = Lt + (ky * 5 + kx) * 4;
                #pragma unroll
                for (int i = 0; i < 2; i++)
                    #pragma unroll
                    for (int j = 0; j < 4; j++)
                        rv[i][j] += lt[ma[i + ky][j + kx]];
            }
        #pragma unroll
        for (int i = 0; i < 2; i++)
            #pragma unroll
            for (int j = 0; j < 4; j++)
                rsm[(y0 + i + 2) * VP + x0 + j + 2] = rv[i][j];
    }
    __syncthreads();   // all msm reads done; qr (alias) writable; rsm visible

    // ---------------- qr = conv(r, q_w); v1 = max_c qr ----------------
    {
        float ra[6][8];
        #pragma unroll
        for (int i = 0; i < 6; i++)
            #pragma unroll
            for (int j = 0; j < 4; j++) {
                float2 p = *(const float2*)(rsm + (y0 + i) * VP + x0 + 2 * j);
                ra[i][2 * j] = p.x; ra[i][2 * j + 1] = p.y;
            }
        float vnew[2][4];
        #pragma unroll
        for (int i = 0; i < 2; i++)
            #pragma unroll
            for (int j = 0; j < 4; j++) vnew[i][j] = -INFINITY;
        #pragma unroll 1
        for (int c = 0; c < 8; c++) {
            float qc[2][4];
            #pragma unroll
            for (int i = 0; i < 2; i++)
                #pragma unroll
                for (int j = 0; j < 4; j++) qc[i][j] = 0.f;
            const float* wc = wq + c * 25;
            #pragma unroll
            for (int ky = 0; ky < 5; ky++)
                #pragma unroll
                for (int kx = 0; kx < 5; kx++) {
                    float wt = wc[ky * 5 + kx];
                    #pragma unroll
                    for (int i = 0; i < 2; i++)
                        #pragma unroll
                        for (int j = 0; j < 4; j++)
                            qc[i][j] += wt * ra[i + ky][j + kx];
                }
            float* qrc = qr + c * 4096;
            #pragma unroll
            for (int i = 0; i < 2; i++)
                *(float4*)(qrc + (y0 + i) * 64 + x0) =
                    make_float4(qc[i][0], qc[i][1], qc[i][2], qc[i][3]);
            #pragma unroll
            for (int i = 0; i < 2; i++)
                #pragma unroll
                for (int j = 0; j < 4; j++)
                    vnew[i][j] = fmaxf(vnew[i][j], qc[i][j]);
        }
        #pragma unroll
        for (int i = 0; i < 2; i++)
            #pragma unroll
            for (int j = 0; j < 4; j++)
                vsm[(y0 + i + 2) * VP + x0 + j + 2] = vnew[i][j];
    }
    __syncthreads();

    // ---------------- 9 value-iteration steps: v <- max_c(qr + conv(v,w)) ----
    for (int k = 0; k < 9; ++k) {
        float va[6][8];
        #pragma unroll
        for (int i = 0; i < 6; i++)
            #pragma unroll
            for (int j = 0; j < 4; j++) {
                float2 p = *(const float2*)(vsm + (y0 + i) * VP + x0 + 2 * j);
                va[i][2 * j] = p.x; va[i][2 * j + 1] = p.y;
            }
        float vnew[2][4];
        #pragma unroll
        for (int i = 0; i < 2; i++)
            #pragma unroll
            for (int j = 0; j < 4; j++) vnew[i][j] = -INFINITY;
        #pragma unroll 1
        for (int c = 0; c < 8; c++) {
            float qc[2][4];
            const float* qrc = qr + c * 4096;
            #pragma unroll
            for (int i = 0; i < 2; i++) {
                float4 q4 = *(const float4*)(qrc + (y0 + i) * 64 + x0);
                qc[i][0] = q4.x; qc[i][1] = q4.y; qc[i][2] = q4.z; qc[i][3] = q4.w;
            }
            const float* wc = ww + c * 25;
            #pragma unroll
            for (int ky = 0; ky < 5; ky++)
                #pragma unroll
                for (int kx = 0; kx < 5; kx++) {
                    float wt = wc[ky * 5 + kx];
                    #pragma unroll
                    for (int i = 0; i < 2; i++)
                        #pragma unroll
                        for (int j = 0; j < 4; j++)
                            qc[i][j] += wt * va[i + ky][j + kx];
                }
            #pragma unroll
            for (int i = 0; i < 2; i++)
                #pragma unroll
                for (int j = 0; j < 4; j++)
                    vnew[i][j] = fmaxf(vnew[i][j], qc[i][j]);
        }
        __syncthreads();   // all v reads complete
        #pragma unroll
        for (int i = 0; i < 2; i++)
            #pragma unroll
            for (int j = 0; j < 4; j++)
                vsm[(y0 + i + 2) * VP + x0 + j + 2] = vnew[i][j];
        __syncthreads();   // new v visible
    }

    // ---------------- final step: q10 = qr + conv(v10,w); out = q10 @ fc^T ----
    {
        float va[6][8];
        #pragma unroll
        for (int i = 0; i < 6; i++)
            #pragma unroll
            for (int j = 0; j < 4; j++) {
                float2 p = *(const float2*)(vsm + (y0 + i) * VP + x0 + 2 * j);
                va[i][2 * j] = p.x; va[i][2 * j + 1] = p.y;
            }
        float oa[2][4][4];
        #pragma unroll
        for (int i = 0; i < 2; i++)
            #pragma unroll
            for (int j = 0; j < 4; j++)
                #pragma unroll
                for (int a = 0; a < 4; a++) oa[i][j][a] = 0.f;
        #pragma unroll 1
        for (int c = 0; c < 8; c++) {
            float qc[2][4];
            const float* qrc = qr + c * 4096;
            #pragma unroll
            for (int i = 0; i < 2; i++) {
                float4 q4 = *(const float4*)(qrc + (y0 + i) * 64 + x0);
                qc[i][0] = q4.x; qc[i][1] = q4.y; qc[i][2] = q4.z; qc[i][3] = q4.w;
            }
            const float* wc = ww + c * 25;
            #pragma unroll
            for (int ky = 0; ky < 5; ky++)
                #pragma unroll
                for (int kx = 0; kx < 5; kx++) {
                    float wt = wc[ky * 5 + kx];
                    #pragma unroll
                    for (int i = 0; i < 2; i++)
                        #pragma unroll
                        for (int j = 0; j < 4; j++)
                            qc[i][j] += wt * va[i + ky][j + kx];
                }
            #pragma unroll
            for (int a = 0; a < 4; a++) {
                float f = fcw[a * 8 + c];
                #pragma unroll
                for (int i = 0; i < 2; i++)
                    #pragma unroll
                    for (int j = 0; j < 4; j++)
                        oa[i][j][a] += qc[i][j] * f;
            }
        }
        float* og = out + (size_t)b * 4096 * 4;
        #pragma unroll
        for (int i = 0; i < 2; i++)
            #pragma unroll
            for (int j = 0; j < 4; j++)
                *(float4*)(og + ((y0 + i) * 64 + x0 + j) * 4) =
                    make_float4(oa[i][j][0], oa[i][j][1], oa[i][j][2], oa[i][j][3]);
    }
}

extern "C" void kernel_launch(void* const* d_in, const int* in_sizes, int n_in,
                              void* d_out, int out_size) {
    cudaFuncSetAttribute(vin_kernel, cudaFuncAttributeMaxDynamicSharedMemorySize,
                         SMEM_BYTES);
    const int B = in_sizes[0] >> 12;   // maze elements / 4096
    vin_kernel<<<B, NTH, SMEM_BYTES>>>(
        (const int*)  d_in[0],  // maze
        (const float*)d_in[1],  // emb
        (const float*)d_in[2],  // encode_w
        (const float*)d_in[3],  // encode_b
        (const float*)d_in[4],  // r_w
        (const float*)d_in[5],  // q_w
        (const float*)d_in[6],  // w
        (const float*)d_in[7],  // fc_w
        (float*)d_out);
}

// round 4
// speedup vs baseline: 1.3111x; 1.3111x over previous
#include <cuda_runtime.h>
#include <cstdint>
#include <math.h>

#define NTH 512
#define VP 72          // padded v/r row pitch (floats)
#define VR 36          // v rows per CTA: 32 own + 2 halo top + 2 halo bottom
#define RROWS 36
#define MROWS 40
#define MP 68

// shared-memory layout (float offsets)
#define OFF_VA 0
#define OFF_VB (VR*VP)                 // 2592
#define OFF_R  (2*VR*VP)               // 5184
#define OFF_M  (3*VR*VP)               // 7776  (ints, 40*68 = 2720)
#define OFF_WQ (OFF_M + MROWS*MP)      // 10496  wqT[25][8]
#define OFF_WW (OFF_WQ + 200)          // 10696  wwT[25][8]
#define OFF_FC (OFF_WW + 200)          // 10896  fcT[8][4]
#define OFF_LT (OFF_FC + 32)           // 10928  LUT[25][4]
#define OFF_WE (OFF_LT + 100)          // 11028  Weff[2][25] (+pad)
#define OFF_BE (OFF_WE + 52)           // 11080
#define OFF_QR 11088                   // qr[8][32][64] = 16384
#define SM_FLOATS (OFF_QR + 8*32*64)   // 27472 floats
#define SMEM_BYTES (SM_FLOATS * 4)     // 109888 B

__device__ __forceinline__ uint32_t smem_u32(const void* p) {
    uint32_t a;
    asm("{ .reg .u64 t; cvta.to.shared.u64 t, %1; cvt.u32.u64 %0, t; }"
        : "=r"(a) : "l"(p));
    return a;
}
__device__ __forceinline__ uint32_t mapa_rank(uint32_t a, uint32_t rk) {
    uint32_t r;
    asm("mapa.shared::cluster.u32 %0, %1, %2;" : "=r"(r) : "r"(a), "r"(rk));
    return r;
}
__device__ __forceinline__ void st_remote_f2(uint32_t a, float x, float y) {
    asm volatile("st.shared::cluster.v2.f32 [%0], {%1,%2};"
                 :: "r"(a), "f"(x), "f"(y) : "memory");
}
#define CSYNC() do { \
    asm volatile("barrier.cluster.arrive.aligned;" ::: "memory"); \
    asm volatile("barrier.cluster.wait.aligned;"   ::: "memory"); } while (0)

__global__ void __cluster_dims__(2,1,1) __launch_bounds__(NTH, 1)
vin_kernel(const int*   __restrict__ maze,
           const float* __restrict__ emb,
           const float* __restrict__ encode_w,
           const float* __restrict__ encode_b,
           const float* __restrict__ r_w,
           const float* __restrict__ q_w,
           const float* __restrict__ w,
           const float* __restrict__ fc_w,
           float* __restrict__ out)
{
    extern __shared__ float sm[];
    float* rsm = sm + OFF_R;
    int*   msm = (int*)(sm + OFF_M);
    float* wqT = sm + OFF_WQ;
    float* wwT = sm + OFF_WW;
    float* fcT = sm + OFF_FC;
    float* Lt  = sm + OFF_LT;
    float* We  = sm + OFF_WE;
    float* qrs = sm + OFF_QR;

    const int tid  = threadIdx.x;
    const int rank = blockIdx.x;       // cluster rank: 0 = rows 0..31, 1 = rows 32..63
    const int b    = blockIdx.y;
    const int tx   = tid & 31;
    const int ty   = tid >> 5;
    const int x0   = tx * 2;           // 2 cols per thread
    const int yo   = ty * 2;           // 2 rows per thread (within own 32)
    const int gy0  = rank * 32;

    const uint32_t my32   = smem_u32(sm);
    const uint32_t peer32 = mapa_rank(my32, rank ^ 1);

    // ---------------- prologue ----------------
    for (int i = tid; i < 200; i += NTH) {
        int c = i / 25, t = i - c * 25;
        wqT[t * 8 + c] = q_w[i];
        wwT[t * 8 + c] = w[i];
    }
    if (tid < 32) { int a = tid >> 3, c = tid & 7; fcT[c * 4 + a] = fc_w[tid]; }
    if (tid >= 64 && tid < 114) {
        int t = tid - 64;
        float s = 0.f;
        #pragma unroll 5
        for (int c = 0; c < 150; ++c) s += r_w[c] * encode_w[c * 50 + t];
        We[t] = s;
    }
    if (tid == 63) {
        float s = 0.f;
        for (int c = 0; c < 150; ++c) s += r_w[c] * encode_b[c];
        sm[OFF_BE] = s;
    }
    for (int i = tid; i < MROWS * MP; i += NTH) msm[i] = 3;  // sentinel
    for (int i = tid; i < VR * VP; i += NTH) {
        sm[OFF_VA + i] = 0.f; sm[OFF_VB + i] = 0.f; rsm[i] = 0.f;
    }
    __syncthreads();

    // LUT: Lt[tap*4 + mv] ; mv==3 sentinel -> 0
    if (tid < 75) {
        int t = tid / 3, mv = tid - t * 3;
        Lt[t * 4 + mv] = We[t] * emb[2 * mv] + We[25 + t] * emb[2 * mv + 1];
        if (mv == 0) Lt[t * 4 + 3] = 0.f;
    }
    // maze rows [gy0-4, gy0+36)
    const int* mz = maze + b * 4096;
    for (int i = tid; i < MROWS * 64; i += NTH) {
        int mr = i >> 6, c = i & 63, g = gy0 - 4 + mr;
        if ((unsigned)g < 64u) msm[mr * MP + c + 2] = mz[g * 64 + c];
    }
    CSYNC();   // local: LUT/maze visible. cluster: peer's v buffers zeroed.

    // ---------------- r = LUT-conv(maze) + b_eff, rows [gy0-2, gy0+34) ----------------
    {
        const float bv = sm[OFF_BE];
        for (int i = tid; i < RROWS * 64; i += NTH) {
            int vr = i >> 6, c = i & 63, g = gy0 - 2 + vr;
            if ((unsigned)g < 64u) {
                float s = bv;
                #pragma unroll
                for (int dy = 0; dy < 5; dy++)
                    #pragma unroll
                    for (int dx = 0; dx < 5; dx++)
                        s += Lt[(dy * 5 + dx) * 4 + msm[(vr + dy) * MP + c + dx]];
                rsm[vr * VP + c + 2] = s;
            }
        }
    }
    __syncthreads();

    // ---------------- qr = conv(r, wq) (to smem, [ch][row][col]); v0 = max_c qr ---------
    {
        float ra[6][6];
        #pragma unroll
        for (int i = 0; i < 6; i++) {
            const float* rw = rsm + (yo + i) * VP + x0;
            float2 p0 = *(const float2*)(rw);
            float2 p1 = *(const float2*)(rw + 2);
            float2 p2 = *(const float2*)(rw + 4);
            ra[i][0] = p0.x; ra[i][1] = p0.y; ra[i][2] = p1.x;
            ra[i][3] = p1.y; ra[i][4] = p2.x; ra[i][5] = p2.y;
        }
        float qv[8][2][2];
        #pragma unroll
        for (int c = 0; c < 8; c++)
            #pragma unroll
            for (int i = 0; i < 2; i++) { qv[c][i][0] = 0.f; qv[c][i][1] = 0.f; }
        #pragma unroll
        for (int ky = 0; ky < 5; ky++)
            #pragma unroll
            for (int kx = 0; kx < 5; kx++) {
                const float4 wa = *(const float4*)(wqT + (ky * 5 + kx) * 8);
                const float4 wb = *(const float4*)(wqT + (ky * 5 + kx) * 8 + 4);
                const float wv[8] = {wa.x, wa.y, wa.z, wa.w, wb.x, wb.y, wb.z, wb.w};
                #pragma unroll
                for (int c = 0; c < 8; c++)
                    #pragma unroll
                    for (int i = 0; i < 2; i++)
                        #pragma unroll
                        for (int j = 0; j < 2; j++)
                            qv[c][i][j] += wv[c] * ra[ky + i][kx + j];
            }
        // store qr, compute v0
        float vn[2][2];
        #pragma unroll
        for (int i = 0; i < 2; i++)
            #pragma unroll
            for (int j = 0; j < 2; j++) vn[i][j] = qv[0][i][j];
        #pragma unroll
        for (int c = 0; c < 8; c++) {
            #pragma unroll
            for (int i = 0; i < 2; i++)
                *(float2*)(qrs + c * 2048 + (yo + i) * 64 + x0) =
                    make_float2(qv[c][i][0], qv[c][i][1]);
            if (c) {
                #pragma unroll
                for (int i = 0; i < 2; i++)
                    #pragma unroll
                    for (int j = 0; j < 2; j++)
                        vn[i][j] = fmaxf(vn[i][j], qv[c][i][j]);
            }
        }
        #pragma unroll
        for (int i = 0; i < 2; i++)
            *(float2*)(sm + OFF_VA + (yo + 2 + i) * VP + x0 + 2) =
                make_float2(vn[i][0], vn[i][1]);
        if (rank == 0 && ty == 15) {      // rows 30,31 -> peer halo rows 0,1
            #pragma unroll
            for (int i = 0; i < 2; i++)
                st_remote_f2(peer32 + (OFF_VA + i * VP + x0 + 2) * 4, vn[i][0], vn[i][1]);
        }
        if (rank == 1 && ty == 0) {       // rows 0,1 -> peer halo rows 34,35
            #pragma unroll
            for (int i = 0; i < 2; i++)
                st_remote_f2(peer32 + (OFF_VA + (34 + i) * VP + x0 + 2) * 4, vn[i][0], vn[i][1]);
        }
    }
    CSYNC();

    // ---------------- 9 value-iteration steps ----------------
    for (int k = 0; k < 9; ++k) {
        const int inOff  = (k & 1) ? OFF_VB : OFF_VA;
        const int outOff = (k & 1) ? OFF_VA : OFF_VB;
        const float* vin = sm + inOff;
        float va[6][6];
        #pragma unroll
        for (int i = 0; i < 6; i++) {
            const float* rw = vin + (yo + i) * VP + x0;
            float2 p0 = *(const float2*)(rw);
            float2 p1 = *(const float2*)(rw + 2);
            float2 p2 = *(const float2*)(rw + 4);
            va[i][0] = p0.x; va[i][1] = p0.y; va[i][2] = p1.x;
            va[i][3] = p1.y; va[i][4] = p2.x; va[i][5] = p2.y;
        }
        float qc[8][2][2];
        #pragma unroll
        for (int c = 0; c < 8; c++)
            #pragma unroll
            for (int i = 0; i < 2; i++) {
                float2 q2 = *(const float2*)(qrs + c * 2048 + (yo + i) * 64 + x0);
                qc[c][i][0] = q2.x; qc[c][i][1] = q2.y;
            }
        #pragma unroll
        for (int ky = 0; ky < 5; ky++)
            #pragma unroll
            for (int kx = 0; kx < 5; kx++) {
                const float4 wa = *(const float4*)(wwT + (ky * 5 + kx) * 8);
                const float4 wb = *(const float4*)(wwT + (ky * 5 + kx) * 8 + 4);
                const float wv[8] = {wa.x, wa.y, wa.z, wa.w, wb.x, wb.y, wb.z, wb.w};
                #pragma unroll
                for (int c = 0; c < 8; c++)
                    #pragma unroll
                    for (int i = 0; i < 2; i++)
                        #pragma unroll
                        for (int j = 0; j < 2; j++)
                            qc[c][i][j] += wv[c] * va[ky + i][kx + j];
            }
        float vn[2][2];
        #pragma unroll
        for (int i = 0; i < 2; i++)
            #pragma unroll
            for (int j = 0; j < 2; j++) {
                float m = qc[0][i][j];
                #pragma unroll
                for (int c = 1; c < 8; c++) m = fmaxf(m, qc[c][i][j]);
                vn[i][j] = m;
            }
        #pragma unroll
        for (int i = 0; i < 2; i++)
            *(float2*)(sm + outOff + (yo + 2 + i) * VP + x0 + 2) =
                make_float2(vn[i][0], vn[i][1]);
        if (rank == 0 && ty == 15) {
            #pragma unroll
            for (int i = 0; i < 2; i++)
                st_remote_f2(peer32 + (outOff + i * VP + x0 + 2) * 4, vn[i][0], vn[i][1]);
        }
        if (rank == 1 && ty == 0) {
            #pragma unroll
            for (int i = 0; i < 2; i++)
                st_remote_f2(peer32 + (outOff + (34 + i) * VP + x0 + 2) * 4, vn[i][0], vn[i][1]);
        }
        CSYNC();
    }

    // ---------------- final: q10 = qr + conv(v9, w); out = q10 @ fc^T --------------
    {
        const float* vin = sm + OFF_VB;   // v9 lives in buffer B (9 odd)
        float va[6][6];
        #pragma unroll
        for (int i = 0; i < 6; i++) {
            const float* rw = vin + (yo + i) * VP + x0;
            float2 p0 = *(const float2*)(rw);
            float2 p1 = *(const float2*)(rw + 2);
            float2 p2 = *(const float2*)(rw + 4);
            va[i][0] = p0.x; va[i][1] = p0.y; va[i][2] = p1.x;
            va[i][3] = p1.y; va[i][4] = p2.x; va[i][5] = p2.y;
        }
        float qc[8][2][2];
        #pragma unroll
        for (int c = 0; c < 8; c++)
            #pragma unroll
            for (int i = 0; i < 2; i++) {
                float2 q2 = *(const float2*)(qrs + c * 2048 + (yo + i) * 64 + x0);
                qc[c][i][0] = q2.x; qc[c][i][1] = q2.y;
            }
        #pragma unroll
        for (int ky = 0; ky < 5; ky++)
            #pragma unroll
            for (int kx = 0; kx < 5; kx++) {
                const float4 wa = *(const float4*)(wwT + (ky * 5 + kx) * 8);
                const float4 wb = *(const float4*)(wwT + (ky * 5 + kx) * 8 + 4);
                const float wv[8] = {wa.x, wa.y, wa.z, wa.w, wb.x, wb.y, wb.z, wb.w};
                #pragma unroll
                for (int c = 0; c < 8; c++)
                    #pragma unroll
                    for (int i = 0; i < 2; i++)
                        #pragma unroll
                        for (int j = 0; j < 2; j++)
                            qc[c][i][j] += wv[c] * va[ky + i][kx + j];
            }
        float4 fr[8];
        #pragma unroll
        for (int c = 0; c < 8; c++) fr[c] = *(const float4*)(fcT + c * 4);
        #pragma unroll
        for (int i = 0; i < 2; i++)
            #pragma unroll
            for (int j = 0; j < 2; j++) {
                float4 o = make_float4(0.f, 0.f, 0.f, 0.f);
                #pragma unroll
                for (int c = 0; c < 8; c++) {
                    o.x += qc[c][i][j] * fr[c].x;
                    o.y += qc[c][i][j] * fr[c].y;
                    o.z += qc[c][i][j] * fr[c].z;
                    o.w += qc[c][i][j] * fr[c].w;
                }
                *(float4*)(out + (((size_t)b * 64 + gy0 + yo + i) * 64 + (x0 + j)) * 4) = o;
            }
    }
}

extern "C" void kernel_launch(void* const* d_in, const int* in_sizes, int n_in,
                              void* d_out, int out_size) {
    cudaFuncSetAttribute(vin_kernel, cudaFuncAttributeMaxDynamicSharedMemorySize,
                         SMEM_BYTES);
    const int B = in_sizes[0] >> 12;   // maze elements / 4096
    dim3 grid(2, B, 1);
    vin_kernel<<<grid, NTH, SMEM_BYTES>>>(
        (const int*)  d_in[0],  // maze
        (const float*)d_in[1],  // emb
        (const float*)d_in[2],  // encode_w
        (const float*)d_in[3],  // encode_b
        (const float*)d_in[4],  // r_w
        (const float*)d_in[5],  // q_w
        (const float*)d_in[6],  // w
        (const float*)d_in[7],  // fc_w
        (float*)d_out);
}